// round 13
// baseline (speedup 1.0000x reference)
#include <cuda_runtime.h>
#include <cstdint>
#include <math.h>

#define B_ 4
#define N_ 4096
#define M_ 1024
#define C_ 384
#define H_ 8
#define HD_ 48
#define KDIM 384

// ---------------------------------------------------------------------------
// Scratch (allocation-free rule: __device__ globals)
// ---------------------------------------------------------------------------
__device__ float g_q  [B_ * (size_t)N_ * C_];      // q projection  [B,N,384]
__device__ float g_kv [B_ * (size_t)M_ * 2 * C_];  // kv projection [B,M,2,384]
__device__ float g_x  [B_ * (size_t)N_ * C_];      // attention out [B,N,384]
__device__ float g_wqt [C_ * C_];                  // Wq^T  (tf32-rounded)
__device__ float g_wkvt[2 * C_ * C_];              // Wkv^T
__device__ float g_wpt [C_ * C_];                  // Wproj^T

// ---------------------------------------------------------------------------
// helpers
// ---------------------------------------------------------------------------
__device__ __forceinline__ float tf32r(float x) {   // round-to-nearest tf32
    uint32_t u;
    asm("cvt.rna.tf32.f32 %0, %1;" : "=r"(u) : "f"(x));
    return __uint_as_float(u);
}
__device__ __forceinline__ float ex2(float x) {
    float y;
    asm("ex2.approx.ftz.f32 %0, %1;" : "=f"(y) : "f"(x));
    return y;
}
// D(16x8) += A(16x8,row) * B(8x8,col); fp32 accum, tf32 inputs. (HW-verified)
__device__ __forceinline__ void mma_tf32(float* d, const uint32_t* a, const uint32_t* b) {
    asm volatile("mma.sync.aligned.m16n8k8.row.col.f32.tf32.tf32.f32 "
                 "{%0,%1,%2,%3}, {%4,%5,%6,%7}, {%8,%9}, {%0,%1,%2,%3};"
                 : "+f"(d[0]), "+f"(d[1]), "+f"(d[2]), "+f"(d[3])
                 : "r"(a[0]), "r"(a[1]), "r"(a[2]), "r"(a[3]),
                   "r"(b[0]), "r"(b[1]));
}

// ---------------------------------------------------------------------------
// Fused weight transposes + tf32 rounding (one launch for Wq, Wkv, Wproj).
// ---------------------------------------------------------------------------
__global__ void transpose_all_kernel(const float* __restrict__ Wq,
                                     const float* __restrict__ Wkv,
                                     const float* __restrict__ Wp,
                                     float* __restrict__ oq,
                                     float* __restrict__ okv,
                                     float* __restrict__ op)
{
    __shared__ float tbuf[32][33];
    const int bid = blockIdx.x;
    const float* in; float* out; int Ncols, tile;
    if (bid < 144)      { in = Wq;  out = oq;  Ncols = 384; tile = bid; }
    else if (bid < 432) { in = Wkv; out = okv; Ncols = 768; tile = bid - 144; }
    else                { in = Wp;  out = op;  Ncols = 384; tile = bid - 432; }
    const int tilesX = Ncols / 32;
    const int n0 = (tile % tilesX) * 32;
    const int k0 = (tile / tilesX) * 32;
    const int x = threadIdx.x, y = threadIdx.y;
    #pragma unroll
    for (int i = 0; i < 32; i += 8)
        tbuf[y + i][x] = in[(size_t)(k0 + y + i) * Ncols + n0 + x];
    __syncthreads();
    #pragma unroll
    for (int i = 0; i < 32; i += 8)
        out[(size_t)(n0 + y + i) * KDIM + k0 + x] = tf32r(tbuf[x][y + i]);
}

// ---------------------------------------------------------------------------
// Tensor-core TF32 GEMM body, 2-stage pipelined (HW-verified mainloop).
// ---------------------------------------------------------------------------
#define GEMM_SMEM_BYTES (2 * 8192 * 4)

template <bool EPI>
__device__ __forceinline__ void gemm_body(
    const float* __restrict__ A, const float* __restrict__ BT,
    float* __restrict__ C, int Ncols, int rowBase, int colBase,
    const float* __restrict__ bias, const float* __restrict__ res,
    float* sm_g)
{
    const int tid = threadIdx.x;
    const int wid = tid >> 5;
    const int lane = tid & 31;
    const int warpM = wid >> 1;
    const int warpN = wid & 1;

    const int f4 = tid & 7;
    const int rRow = tid >> 3;
    const int ki_s = f4 >> 1;
    const int rA = rRow & 15;
    const int j0A = (rA >> 3) + ((f4 & 1) << 1);
    const int nlB = rRow & 7;
    const int jB = f4 & 1;
    int baseA[4], baseB[4];
    #pragma unroll
    for (int it = 0; it < 4; it++) {
        int mi = (rRow >> 4) + it * 2;
        baseA[it] = (mi * 4 + ki_s) * 128 + (rA & 7) * 16 + j0A;
        int ni = (rRow >> 3) + it * 4;
        baseB[it] = (ni * 4 + ki_s) * 64 + nlB * 8 + jB;
    }
    const float* Ap = A + (size_t)(rowBase + rRow) * KDIM + f4 * 4;
    const float* Bp = BT + (size_t)(colBase + rRow) * KDIM + f4 * 4;

    float4 aReg[4], bReg[4];
    #pragma unroll
    for (int it = 0; it < 4; it++) {
        aReg[it] = *reinterpret_cast<const float4*>(Ap + (size_t)it * 32 * KDIM);
        bReg[it] = *reinterpret_cast<const float4*>(Bp + (size_t)it * 32 * KDIM);
    }
    {
        float* sA = sm_g;
        float* sB = sm_g + 4096;
        #pragma unroll
        for (int it = 0; it < 4; it++) {
            float va[4] = {tf32r(aReg[it].x), tf32r(aReg[it].y),
                           tf32r(aReg[it].z), tf32r(aReg[it].w)};
            float vb[4] = {bReg[it].x, bReg[it].y, bReg[it].z, bReg[it].w};
            #pragma unroll
            for (int i = 0; i < 4; i++) {
                sA[baseA[it] + i * 4] = va[i];
                sB[baseB[it] + i * 2] = vb[i];
            }
        }
    }
    __syncthreads();

    float acc[2][8][4];
    #pragma unroll
    for (int i = 0; i < 2; i++)
        #pragma unroll
        for (int j = 0; j < 8; j++)
            #pragma unroll
            for (int r = 0; r < 4; r++) acc[i][j][r] = 0.f;

    for (int c = 0; c < 12; c++) {
        float* sA = sm_g + (c & 1) * 8192;
        float* sB = sA + 4096;

        if (c < 11) {
            const int k0 = (c + 1) * 32;
            #pragma unroll
            for (int it = 0; it < 4; it++) {
                aReg[it] = *reinterpret_cast<const float4*>(
                    Ap + (size_t)it * 32 * KDIM + k0);
                bReg[it] = *reinterpret_cast<const float4*>(
                    Bp + (size_t)it * 32 * KDIM + k0);
            }
        }

        #pragma unroll
        for (int ki = 0; ki < 4; ki++) {
            uint32_t af[2][4];
            #pragma unroll
            for (int mi2 = 0; mi2 < 2; mi2++) {
                float4 t = *reinterpret_cast<const float4*>(
                    &sA[((warpM * 2 + mi2) * 4 + ki) * 128 + lane * 4]);
                af[mi2][0] = __float_as_uint(t.x);
                af[mi2][1] = __float_as_uint(t.y);
                af[mi2][2] = __float_as_uint(t.z);
                af[mi2][3] = __float_as_uint(t.w);
            }
            #pragma unroll
            for (int nj = 0; nj < 8; nj++) {
                float2 t = *reinterpret_cast<const float2*>(
                    &sB[((warpN * 8 + nj) * 4 + ki) * 64 + lane * 2]);
                uint32_t bf[2] = {__float_as_uint(t.x), __float_as_uint(t.y)};
                mma_tf32(acc[0][nj], af[0], bf);
                mma_tf32(acc[1][nj], af[1], bf);
            }
        }

        if (c < 11) {
            float* dA = sm_g + ((c + 1) & 1) * 8192;
            float* dB = dA + 4096;
            #pragma unroll
            for (int it = 0; it < 4; it++) {
                float va[4] = {tf32r(aReg[it].x), tf32r(aReg[it].y),
                               tf32r(aReg[it].z), tf32r(aReg[it].w)};
                float vb[4] = {bReg[it].x, bReg[it].y, bReg[it].z, bReg[it].w};
                #pragma unroll
                for (int i = 0; i < 4; i++) {
                    dA[baseA[it] + i * 4] = va[i];
                    dB[baseB[it] + i * 2] = vb[i];
                }
            }
        }
        __syncthreads();
    }

    const int groupID = lane >> 2;
    const int tig = lane & 3;
    #pragma unroll
    for (int mi2 = 0; mi2 < 2; mi2++) {
        const int row0 = rowBase + warpM * 32 + mi2 * 16 + groupID;
        #pragma unroll
        for (int nj = 0; nj < 8; nj++) {
            const int col = colBase + warpN * 64 + nj * 8 + tig * 2;
            float2 lo = make_float2(acc[mi2][nj][0], acc[mi2][nj][1]);
            float2 hi = make_float2(acc[mi2][nj][2], acc[mi2][nj][3]);
            if (EPI) {
                float2 bz = *reinterpret_cast<const float2*>(&bias[col]);
                float2 r0 = *reinterpret_cast<const float2*>(
                    &res[(size_t)row0 * Ncols + col]);
                float2 r1 = *reinterpret_cast<const float2*>(
                    &res[(size_t)(row0 + 8) * Ncols + col]);
                lo.x += bz.x + r0.x; lo.y += bz.y + r0.y;
                hi.x += bz.x + r1.x; hi.y += bz.y + r1.y;
            }
            *reinterpret_cast<float2*>(&C[(size_t)row0 * Ncols + col]) = lo;
            *reinterpret_cast<float2*>(&C[(size_t)(row0 + 8) * Ncols + col]) = hi;
        }
    }
}

// gemm1 + gemm2 in ONE launch; 2 CTAs/SM target (128 regs, 64KB smem each).
__global__ __launch_bounds__(256, 2) void tc_gemm12_kernel(
    const float* __restrict__ A1, const float* __restrict__ BT1, float* __restrict__ C1,
    const float* __restrict__ A2, const float* __restrict__ BT2, float* __restrict__ C2)
{
    extern __shared__ __align__(16) float sm_g[];
    const int bid = blockIdx.x;
    if (bid < 384) {
        gemm_body<false>(A1, BT1, C1, C_, (bid / 3) * 128, (bid % 3) * 128,
                         nullptr, nullptr, sm_g);
    } else {
        const int t = bid - 384;
        gemm_body<false>(A2, BT2, C2, 2 * C_, (t / 6) * 128, (t % 6) * 128,
                         nullptr, nullptr, sm_g);
    }
}

// gemm3 (with bias + residual epilogue), 2 CTAs/SM target.
__global__ __launch_bounds__(256, 2) void tc_gemm3_kernel(
    const float* __restrict__ A, const float* __restrict__ BT, float* __restrict__ C,
    const float* __restrict__ bias, const float* __restrict__ res)
{
    extern __shared__ __align__(16) float sm_g[];
    gemm_body<true>(A, BT, C, C_, (int)blockIdx.y * 128, (int)blockIdx.x * 128,
                    bias, res, sm_g);
}

// ---------------------------------------------------------------------------
// Tensor-core flash attention, 32 query rows/warp, 2-stage KV pipeline,
// max-free softmax. This round: sP row stride 68 floats (PV LDS.32 reads
// conflict-free: bank = 4g+t covers all 32), KV scatter hoisted before PV
// so its STS latency drains under the PV MMAs instead of before the barrier.
// Smem (floats): KV 2x6144 @0 ; sQ [96 atoms][128] @12288 (dead after frag
// load) ; sP [256][68] @12288 (aliases sQ). Total 29696 f = 118784 B.
// ---------------------------------------------------------------------------
#define PSTR 68
#define ATTN_SMEM_BYTES (29696 * 4)

__device__ __forceinline__ void attn_ldg_kv(
    const float* __restrict__ kvbase, int m0, int tid,
    float4* kf4, float4* vf4)
{
    #pragma unroll
    for (int it = 0; it < 3; it++) {
        int idx = tid + it * 256;
        int n = idx / 12, f4 = idx - n * 12;
        const float* p = kvbase + (size_t)(m0 + n) * 2 * C_ + f4 * 4;
        kf4[it] = *reinterpret_cast<const float4*>(p);
        vf4[it] = *reinterpret_cast<const float4*>(p + C_);
    }
}
__device__ __forceinline__ void attn_scatter_kv(
    float* __restrict__ sK, int tid, const float4* kf4, const float4* vf4)
{
    float* sV = sK + 3072;
    #pragma unroll
    for (int it = 0; it < 3; it++) {
        int idx = tid + it * 256;
        int n = idx / 12, f4 = idx - n * 12;
        float kf[4] = {tf32r(kf4[it].x), tf32r(kf4[it].y),
                       tf32r(kf4[it].z), tf32r(kf4[it].w)};
        float vf[4] = {tf32r(vf4[it].x), tf32r(vf4[it].y),
                       tf32r(vf4[it].z), tf32r(vf4[it].w)};
        int ni = n >> 3, nl = n & 7;
        int ki = f4 >> 1, j = f4 & 1;
        int kb = (ni * 6 + ki) * 64 + nl * 8 + j;
        #pragma unroll
        for (int i = 0; i < 4; i++)
            sK[kb + i * 2] = kf[i];
        int kiv = n >> 3, tv = n & 3, jv = (n & 7) >> 2;
        #pragma unroll
        for (int i = 0; i < 4; i++) {
            int d = f4 * 4 + i;
            sV[((d >> 3) * 8 + kiv) * 64 + ((d & 7) * 4 + tv) * 2 + jv] = vf[i];
        }
    }
}

__global__ __launch_bounds__(256, 1) void attn_mma_kernel(
    const float* __restrict__ q, const float* __restrict__ kv,
    float* __restrict__ x)
{
    extern __shared__ __align__(16) float sm[];
    float* sKV = sm;            // 2 x 6144
    float* sQ  = sm + 12288;    // [mi*6+ki][128], mi 0..15
    float* sP  = sm + 12288;    // [256][68] (aliases sQ)

    const int tid = threadIdx.x;
    const int wid = tid >> 5;
    const int lane = tid & 31;
    const int g = lane >> 2;
    const int t = lane & 3;
    const int b = blockIdx.z, h = blockIdx.y;
    const int n0 = blockIdx.x * 256;
    const float qscale = 0.144337567297406441127f * 1.44269504088896340736f;

    // ---- stage Q into A-fragment-shuffled layout ----
    {
        const float* qbase = q + ((size_t)(b * N_ + n0)) * C_ + h * HD_;
        #pragma unroll
        for (int it = 0; it < 12; it++) {
            int idx = tid + it * 256;
            int m = idx / 12, f4 = idx - m * 12;
            float4 v = *reinterpret_cast<const float4*>(qbase + (size_t)m * C_ + f4 * 4);
            float vf[4] = {tf32r(v.x * qscale), tf32r(v.y * qscale),
                           tf32r(v.z * qscale), tf32r(v.w * qscale)};
            int mi = m >> 4, r = m & 15;
            int ki = f4 >> 1;
            int j0 = (r >> 3) + ((f4 & 1) << 1);
            int base = (mi * 6 + ki) * 128 + (r & 7) * 16 + j0;
            #pragma unroll
            for (int i = 0; i < 4; i++)
                sQ[base + i * 4] = vf[i];
        }
    }
    __syncthreads();

    uint32_t qf[2][6][4];
    #pragma unroll
    for (int mi2 = 0; mi2 < 2; mi2++)
        #pragma unroll
        for (int ki = 0; ki < 6; ki++) {
            float4 tq = *reinterpret_cast<const float4*>(
                &sQ[((wid * 2 + mi2) * 6 + ki) * 128 + lane * 4]);
            qf[mi2][ki][0] = __float_as_uint(tq.x);
            qf[mi2][ki][1] = __float_as_uint(tq.y);
            qf[mi2][ki][2] = __float_as_uint(tq.z);
            qf[mi2][ki][3] = __float_as_uint(tq.w);
        }

    const float* kvbase = kv + ((size_t)(b * M_)) * 2 * C_ + h * HD_;
    float4 kf4[3], vf4[3];
    attn_ldg_kv(kvbase, 0, tid, kf4, vf4);
    attn_scatter_kv(sKV, tid, kf4, vf4);
    __syncthreads();   // Q frags read + buf0 staged

    float accO[2][6][4];
    #pragma unroll
    for (int mi2 = 0; mi2 < 2; mi2++)
        #pragma unroll
        for (int ni = 0; ni < 6; ni++)
            #pragma unroll
            for (int r = 0; r < 4; r++) accO[mi2][ni][r] = 0.f;
    float lp[2][2] = {{0.f, 0.f}, {0.f, 0.f}};   // per-lane partial l sums

    for (int c = 0; c < 16; c++) {
        float* sK = sKV + (c & 1) * 6144;
        float* sV = sK + 3072;

        if (c < 15)
            attn_ldg_kv(kvbase, (c + 1) * 64, tid, kf4, vf4);

        // ---- QK^T: S[32 x 64] per warp ----
        float accS[2][8][4];
        #pragma unroll
        for (int mi2 = 0; mi2 < 2; mi2++)
            #pragma unroll
            for (int nj = 0; nj < 8; nj++)
                #pragma unroll
                for (int r = 0; r < 4; r++) accS[mi2][nj][r] = 0.f;
        #pragma unroll
        for (int nj = 0; nj < 8; nj++) {
            #pragma unroll
            for (int ki = 0; ki < 6; ki++) {
                float2 tb = *reinterpret_cast<const float2*>(
                    &sK[(nj * 6 + ki) * 64 + lane * 2]);
                uint32_t bf[2] = {__float_as_uint(tb.x), __float_as_uint(tb.y)};
                mma_tf32(accS[0][nj], qf[0][ki], bf);
                mma_tf32(accS[1][nj], qf[1][ki], bf);
            }
        }

        // ---- max-free softmax: p = exp2(s) ----
        #pragma unroll
        for (int mi2 = 0; mi2 < 2; mi2++) {
            float* pr0 = &sP[(wid * 32 + mi2 * 16 + g) * PSTR];
            float* pr1 = pr0 + 8 * PSTR;
            float a0 = 0.f, a1 = 0.f;
            #pragma unroll
            for (int nj = 0; nj < 8; nj++) {
                float p0 = tf32r(ex2(accS[mi2][nj][0]));
                float p1 = tf32r(ex2(accS[mi2][nj][1]));
                float p2 = tf32r(ex2(accS[mi2][nj][2]));
                float p3 = tf32r(ex2(accS[mi2][nj][3]));
                a0 += p0 + p1;
                a1 += p2 + p3;
                *reinterpret_cast<float2*>(&pr0[nj * 8 + 2 * t]) = make_float2(p0, p1);
                *reinterpret_cast<float2*>(&pr1[nj * 8 + 2 * t]) = make_float2(p2, p3);
            }
            lp[mi2][0] += a0;
            lp[mi2][1] += a1;
        }
        __syncwarp();   // sP rows are warp-private

        // ---- scatter prefetched KV into other buffer (drains under PV) ----
        if (c < 15)
            attn_scatter_kv(sKV + ((c + 1) & 1) * 6144, tid, kf4, vf4);

        // ---- PV: O[32 x 48] += P[32 x 64] @ V[64 x 48] ----
        #pragma unroll
        for (int ki = 0; ki < 8; ki++) {
            uint32_t af[2][4];
            #pragma unroll
            for (int mi2 = 0; mi2 < 2; mi2++) {
                const float* par0 = &sP[(wid * 32 + mi2 * 16 + g) * PSTR];
                const float* par1 = par0 + 8 * PSTR;
                af[mi2][0] = __float_as_uint(par0[ki * 8 + t]);
                af[mi2][1] = __float_as_uint(par1[ki * 8 + t]);
                af[mi2][2] = __float_as_uint(par0[ki * 8 + t + 4]);
                af[mi2][3] = __float_as_uint(par1[ki * 8 + t + 4]);
            }
            #pragma unroll
            for (int ni = 0; ni < 6; ni++) {
                float2 tb = *reinterpret_cast<const float2*>(
                    &sV[(ni * 8 + ki) * 64 + lane * 2]);
                uint32_t bf[2] = {__float_as_uint(tb.x), __float_as_uint(tb.y)};
                mma_tf32(accO[0][ni], af[0], bf);
                mma_tf32(accO[1][ni], af[1], bf);
            }
        }

        __syncthreads();
    }

    // ---- final l reduction (quad lanes) + normalize + store ----
    #pragma unroll
    for (int mi2 = 0; mi2 < 2; mi2++) {
        float l0 = lp[mi2][0], l1 = lp[mi2][1];
        l0 += __shfl_xor_sync(0xffffffffu, l0, 1);
        l0 += __shfl_xor_sync(0xffffffffu, l0, 2);
        l1 += __shfl_xor_sync(0xffffffffu, l1, 1);
        l1 += __shfl_xor_sync(0xffffffffu, l1, 2);
        const float inv0 = 1.0f / l0;
        const float inv1 = 1.0f / l1;
        const int row0 = n0 + wid * 32 + mi2 * 16 + g;
        float* xp0 = x + ((size_t)(b * N_ + row0)) * C_ + h * HD_;
        float* xp1 = xp0 + (size_t)8 * C_;
        #pragma unroll
        for (int ni = 0; ni < 6; ni++) {
            *reinterpret_cast<float2*>(&xp0[ni * 8 + 2 * t]) =
                make_float2(accO[mi2][ni][0] * inv0, accO[mi2][ni][1] * inv0);
            *reinterpret_cast<float2*>(&xp1[ni * 8 + 2 * t]) =
                make_float2(accO[mi2][ni][2] * inv1, accO[mi2][ni][3] * inv1);
        }
    }
}

// ---------------------------------------------------------------------------
// Launch
// ---------------------------------------------------------------------------
extern "C" void kernel_launch(void* const* d_in, const int* in_sizes, int n_in,
                              void* d_out, int out_size)
{
    const float* q_x   = (const float*)d_in[0];  // [4,4096,384]
    const float* kv_x  = (const float*)d_in[1];  // [4,1024,384]
    const float* Wq    = (const float*)d_in[2];  // [384,384]
    const float* Wkv   = (const float*)d_in[3];  // [384,768]
    const float* Wproj = (const float*)d_in[4];  // [384,384]
    const float* bproj = (const float*)d_in[5];  // [384]
    float* out = (float*)d_out;                  // [4,4096,384]

    float *gq, *gkv, *gx, *gwqt, *gwkvt, *gwpt;
    cudaGetSymbolAddress((void**)&gq,   g_q);
    cudaGetSymbolAddress((void**)&gkv,  g_kv);
    cudaGetSymbolAddress((void**)&gx,   g_x);
    cudaGetSymbolAddress((void**)&gwqt, g_wqt);
    cudaGetSymbolAddress((void**)&gwkvt,g_wkvt);
    cudaGetSymbolAddress((void**)&gwpt, g_wpt);

    cudaFuncSetAttribute(attn_mma_kernel,
                         cudaFuncAttributeMaxDynamicSharedMemorySize,
                         ATTN_SMEM_BYTES);
    cudaFuncSetAttribute(tc_gemm12_kernel,
                         cudaFuncAttributeMaxDynamicSharedMemorySize,
                         GEMM_SMEM_BYTES);
    cudaFuncSetAttribute(tc_gemm3_kernel,
                         cudaFuncAttributeMaxDynamicSharedMemorySize,
                         GEMM_SMEM_BYTES);

    // 0) all three weight transposes in one launch
    transpose_all_kernel<<<576, dim3(32, 8)>>>(Wq, Wkv, Wproj, gwqt, gwkvt, gwpt);

    // 1+2) q and kv projections in one launch (576 flat CTAs)
    tc_gemm12_kernel<<<576, 256, GEMM_SMEM_BYTES>>>(
        q_x, gwqt, gq, kv_x, gwkvt, gkv);

    // 3) attention -> g_x [B,N,384]
    attn_mma_kernel<<<dim3(N_ / 256, H_, B_), 256, ATTN_SMEM_BYTES>>>(gq, gkv, gx);

    // 4) out = g_x @ Wproj + bproj + g_q
    tc_gemm3_kernel<<<dim3(3, 128), 256, GEMM_SMEM_BYTES>>>(
        gx, gwpt, out, bproj, gq);
}

// round 14
// speedup vs baseline: 1.4996x; 1.4996x over previous
#include <cuda_runtime.h>
#include <cuda_fp16.h>
#include <cstdint>
#include <math.h>

#define B_ 4
#define N_ 4096
#define M_ 1024
#define C_ 384
#define H_ 8
#define HD_ 48
#define KDIM 384

// ---------------------------------------------------------------------------
// Scratch (allocation-free rule: __device__ globals)
// ---------------------------------------------------------------------------
__device__ float g_q  [B_ * (size_t)N_ * C_];      // q projection  [B,N,384]
__device__ float g_kv [B_ * (size_t)M_ * 2 * C_];  // kv projection [B,M,2,384]
__device__ float g_x  [B_ * (size_t)N_ * C_];      // attention out [B,N,384]
__device__ float g_wqt [C_ * C_];                  // Wq^T  (tf32-rounded)
__device__ float g_wkvt[2 * C_ * C_];              // Wkv^T
__device__ float g_wpt [C_ * C_];                  // Wproj^T

// ---------------------------------------------------------------------------
// helpers
// ---------------------------------------------------------------------------
__device__ __forceinline__ float tf32r(float x) {   // round-to-nearest tf32
    uint32_t u;
    asm("cvt.rna.tf32.f32 %0, %1;" : "=r"(u) : "f"(x));
    return __uint_as_float(u);
}
__device__ __forceinline__ float ex2(float x) {
    float y;
    asm("ex2.approx.ftz.f32 %0, %1;" : "=f"(y) : "f"(x));
    return y;
}
__device__ __forceinline__ uint32_t packh2(float lo, float hi) {
    __half2 h = __floats2half2_rn(lo, hi);
    return *reinterpret_cast<uint32_t*>(&h);
}
// tf32: D(16x8) += A(16x8) * B(8x8)  (HW-verified)
__device__ __forceinline__ void mma_tf32(float* d, const uint32_t* a, const uint32_t* b) {
    asm volatile("mma.sync.aligned.m16n8k8.row.col.f32.tf32.tf32.f32 "
                 "{%0,%1,%2,%3}, {%4,%5,%6,%7}, {%8,%9}, {%0,%1,%2,%3};"
                 : "+f"(d[0]), "+f"(d[1]), "+f"(d[2]), "+f"(d[3])
                 : "r"(a[0]), "r"(a[1]), "r"(a[2]), "r"(a[3]),
                   "r"(b[0]), "r"(b[1]));
}
// fp16: D(16x8) += A(16x16) * B(16x8), fp32 accumulate
__device__ __forceinline__ void mma_f16(float* d, const uint32_t* a, const uint32_t* b) {
    asm volatile("mma.sync.aligned.m16n8k16.row.col.f32.f16.f16.f32 "
                 "{%0,%1,%2,%3}, {%4,%5,%6,%7}, {%8,%9}, {%0,%1,%2,%3};"
                 : "+f"(d[0]), "+f"(d[1]), "+f"(d[2]), "+f"(d[3])
                 : "r"(a[0]), "r"(a[1]), "r"(a[2]), "r"(a[3]),
                   "r"(b[0]), "r"(b[1]));
}

// ---------------------------------------------------------------------------
// Fused weight transposes + tf32 rounding (one launch).
// ---------------------------------------------------------------------------
__global__ void transpose_all_kernel(const float* __restrict__ Wq,
                                     const float* __restrict__ Wkv,
                                     const float* __restrict__ Wp,
                                     float* __restrict__ oq,
                                     float* __restrict__ okv,
                                     float* __restrict__ op)
{
    __shared__ float tbuf[32][33];
    const int bid = blockIdx.x;
    const float* in; float* out; int Ncols, tile;
    if (bid < 144)      { in = Wq;  out = oq;  Ncols = 384; tile = bid; }
    else if (bid < 432) { in = Wkv; out = okv; Ncols = 768; tile = bid - 144; }
    else                { in = Wp;  out = op;  Ncols = 384; tile = bid - 432; }
    const int tilesX = Ncols / 32;
    const int n0 = (tile % tilesX) * 32;
    const int k0 = (tile / tilesX) * 32;
    const int x = threadIdx.x, y = threadIdx.y;
    #pragma unroll
    for (int i = 0; i < 32; i += 8)
        tbuf[y + i][x] = in[(size_t)(k0 + y + i) * Ncols + n0 + x];
    __syncthreads();
    #pragma unroll
    for (int i = 0; i < 32; i += 8)
        out[(size_t)(n0 + y + i) * KDIM + k0 + x] = tf32r(tbuf[x][y + i]);
}

// ---------------------------------------------------------------------------
// Tensor-core TF32 GEMM body, 2-stage pipelined (HW-verified R12 config).
// ---------------------------------------------------------------------------
#define GEMM_SMEM_BYTES (2 * 8192 * 4)

template <bool EPI>
__device__ __forceinline__ void gemm_body(
    const float* __restrict__ A, const float* __restrict__ BT,
    float* __restrict__ C, int Ncols, int rowBase, int colBase,
    const float* __restrict__ bias, const float* __restrict__ res,
    float* sm_g)
{
    const int tid = threadIdx.x;
    const int wid = tid >> 5;
    const int lane = tid & 31;
    const int warpM = wid >> 1;
    const int warpN = wid & 1;

    const int f4 = tid & 7;
    const int rRow = tid >> 3;
    const int ki_s = f4 >> 1;
    const int rA = rRow & 15;
    const int j0A = (rA >> 3) + ((f4 & 1) << 1);
    const int nlB = rRow & 7;
    const int jB = f4 & 1;
    int baseA[4], baseB[4];
    #pragma unroll
    for (int it = 0; it < 4; it++) {
        int mi = (rRow >> 4) + it * 2;
        baseA[it] = (mi * 4 + ki_s) * 128 + (rA & 7) * 16 + j0A;
        int ni = (rRow >> 3) + it * 4;
        baseB[it] = (ni * 4 + ki_s) * 64 + nlB * 8 + jB;
    }
    const float* Ap = A + (size_t)(rowBase + rRow) * KDIM + f4 * 4;
    const float* Bp = BT + (size_t)(colBase + rRow) * KDIM + f4 * 4;

    float4 aReg[4], bReg[4];
    #pragma unroll
    for (int it = 0; it < 4; it++) {
        aReg[it] = *reinterpret_cast<const float4*>(Ap + (size_t)it * 32 * KDIM);
        bReg[it] = *reinterpret_cast<const float4*>(Bp + (size_t)it * 32 * KDIM);
    }
    {
        float* sA = sm_g;
        float* sB = sm_g + 4096;
        #pragma unroll
        for (int it = 0; it < 4; it++) {
            float va[4] = {tf32r(aReg[it].x), tf32r(aReg[it].y),
                           tf32r(aReg[it].z), tf32r(aReg[it].w)};
            float vb[4] = {bReg[it].x, bReg[it].y, bReg[it].z, bReg[it].w};
            #pragma unroll
            for (int i = 0; i < 4; i++) {
                sA[baseA[it] + i * 4] = va[i];
                sB[baseB[it] + i * 2] = vb[i];
            }
        }
    }
    __syncthreads();

    float acc[2][8][4];
    #pragma unroll
    for (int i = 0; i < 2; i++)
        #pragma unroll
        for (int j = 0; j < 8; j++)
            #pragma unroll
            for (int r = 0; r < 4; r++) acc[i][j][r] = 0.f;

    for (int c = 0; c < 12; c++) {
        float* sA = sm_g + (c & 1) * 8192;
        float* sB = sA + 4096;

        if (c < 11) {
            const int k0 = (c + 1) * 32;
            #pragma unroll
            for (int it = 0; it < 4; it++) {
                aReg[it] = *reinterpret_cast<const float4*>(
                    Ap + (size_t)it * 32 * KDIM + k0);
                bReg[it] = *reinterpret_cast<const float4*>(
                    Bp + (size_t)it * 32 * KDIM + k0);
            }
        }

        #pragma unroll
        for (int ki = 0; ki < 4; ki++) {
            uint32_t af[2][4];
            #pragma unroll
            for (int mi2 = 0; mi2 < 2; mi2++) {
                float4 t = *reinterpret_cast<const float4*>(
                    &sA[((warpM * 2 + mi2) * 4 + ki) * 128 + lane * 4]);
                af[mi2][0] = __float_as_uint(t.x);
                af[mi2][1] = __float_as_uint(t.y);
                af[mi2][2] = __float_as_uint(t.z);
                af[mi2][3] = __float_as_uint(t.w);
            }
            #pragma unroll
            for (int nj = 0; nj < 8; nj++) {
                float2 t = *reinterpret_cast<const float2*>(
                    &sB[((warpN * 8 + nj) * 4 + ki) * 64 + lane * 2]);
                uint32_t bf[2] = {__float_as_uint(t.x), __float_as_uint(t.y)};
                mma_tf32(acc[0][nj], af[0], bf);
                mma_tf32(acc[1][nj], af[1], bf);
            }
        }

        if (c < 11) {
            float* dA = sm_g + ((c + 1) & 1) * 8192;
            float* dB = dA + 4096;
            #pragma unroll
            for (int it = 0; it < 4; it++) {
                float va[4] = {tf32r(aReg[it].x), tf32r(aReg[it].y),
                               tf32r(aReg[it].z), tf32r(aReg[it].w)};
                float vb[4] = {bReg[it].x, bReg[it].y, bReg[it].z, bReg[it].w};
                #pragma unroll
                for (int i = 0; i < 4; i++) {
                    dA[baseA[it] + i * 4] = va[i];
                    dB[baseB[it] + i * 2] = vb[i];
                }
            }
        }
        __syncthreads();
    }

    const int groupID = lane >> 2;
    const int tig = lane & 3;
    #pragma unroll
    for (int mi2 = 0; mi2 < 2; mi2++) {
        const int row0 = rowBase + warpM * 32 + mi2 * 16 + groupID;
        #pragma unroll
        for (int nj = 0; nj < 8; nj++) {
            const int col = colBase + warpN * 64 + nj * 8 + tig * 2;
            float2 lo = make_float2(acc[mi2][nj][0], acc[mi2][nj][1]);
            float2 hi = make_float2(acc[mi2][nj][2], acc[mi2][nj][3]);
            if (EPI) {
                float2 bz = *reinterpret_cast<const float2*>(&bias[col]);
                float2 r0 = *reinterpret_cast<const float2*>(
                    &res[(size_t)row0 * Ncols + col]);
                float2 r1 = *reinterpret_cast<const float2*>(
                    &res[(size_t)(row0 + 8) * Ncols + col]);
                lo.x += bz.x + r0.x; lo.y += bz.y + r0.y;
                hi.x += bz.x + r1.x; hi.y += bz.y + r1.y;
            }
            *reinterpret_cast<float2*>(&C[(size_t)row0 * Ncols + col]) = lo;
            *reinterpret_cast<float2*>(&C[(size_t)(row0 + 8) * Ncols + col]) = hi;
        }
    }
}

__global__ __launch_bounds__(256) void tc_gemm12_kernel(
    const float* __restrict__ A1, const float* __restrict__ BT1, float* __restrict__ C1,
    const float* __restrict__ A2, const float* __restrict__ BT2, float* __restrict__ C2)
{
    extern __shared__ __align__(16) float sm_g[];
    const int bid = blockIdx.x;
    if (bid < 384) {
        gemm_body<false>(A1, BT1, C1, C_, (bid / 3) * 128, (bid % 3) * 128,
                         nullptr, nullptr, sm_g);
    } else {
        const int t = bid - 384;
        gemm_body<false>(A2, BT2, C2, 2 * C_, (t / 6) * 128, (t % 6) * 128,
                         nullptr, nullptr, sm_g);
    }
}

__global__ __launch_bounds__(256) void tc_gemm3_kernel(
    const float* __restrict__ A, const float* __restrict__ BT, float* __restrict__ C,
    const float* __restrict__ bias, const float* __restrict__ res)
{
    extern __shared__ __align__(16) float sm_g[];
    gemm_body<true>(A, BT, C, C_, (int)blockIdx.y * 128, (int)blockIdx.x * 128,
                    bias, res, sm_g);
}

// ---------------------------------------------------------------------------
// FP16 tensor-core flash attention, register-resident P.
// CTA: 256 thr = 8 warps; 256 queries x 1 head; 64-key chunks, 2-stage KV.
// m16n8k16.f16 with fp32 accumulate. The fp16 C-fragment of S has exactly
// the fp16 A-fragment layout of P, so softmax packs ex2(S) pairs into half2
// registers that feed PV directly — P never touches smem.
// Smem (uint32): sKV 2 x (K 1536 + V 1536) @0 ; sQ 48 atoms x 128 @6144.
// Total 12288 u32 = 48 KB.
// ---------------------------------------------------------------------------
#define ATTN_SMEM_BYTES (12288 * 4)

__device__ __forceinline__ void attn_ldg_kv(
    const float* __restrict__ kvbase, int m0, int tid,
    float4* kf4, float4* vf4)
{
    #pragma unroll
    for (int it = 0; it < 3; it++) {
        int idx = tid + it * 256;
        int n = idx / 12, f4 = idx - n * 12;
        const float* p = kvbase + (size_t)(m0 + n) * 2 * C_ + f4 * 4;
        kf4[it] = *reinterpret_cast<const float4*>(p);
        vf4[it] = *reinterpret_cast<const float4*>(p + C_);
    }
}

// Scatter K into fp16 B-frag atoms [(nj*3+ki)*64], V into [(ni*4+kv)*64].
__device__ __forceinline__ void attn_scatter_kv(
    uint32_t* __restrict__ sKb, int tid, const float4* kf4, const float4* vf4)
{
    __half* sVh = reinterpret_cast<__half*>(sKb + 1536);
    #pragma unroll
    for (int it = 0; it < 3; it++) {
        int idx = tid + it * 256;
        int n = idx / 12, f4 = idx - n * 12;
        // ---- K: key n, dims 4f4..4f4+3 -> two half2 ----
        {
            int nj = n >> 3, g = n & 7, ki = f4 >> 2;
            int j = (f4 >> 1) & 1, t0 = 2 * (f4 & 1);
            int kb = (nj * 3 + ki) * 64 + j;
            sKb[kb + (g * 4 + t0) * 2]     = packh2(kf4[it].x, kf4[it].y);
            sKb[kb + (g * 4 + t0 + 1) * 2] = packh2(kf4[it].z, kf4[it].w);
        }
        // ---- V: key n, dims 4f4..4f4+3 -> four half stores ----
        {
            int kv = n >> 4, lk = n & 15;
            int jv = lk >> 3, tv = (lk & 7) >> 1, pos = lk & 1;
            float vv[4] = {vf4[it].x, vf4[it].y, vf4[it].z, vf4[it].w};
            #pragma unroll
            for (int i = 0; i < 4; i++) {
                int d = 4 * f4 + i;
                int ni = d >> 3, gd = d & 7;
                sVh[(((ni * 4 + kv) * 64 + (gd * 4 + tv) * 2 + jv) << 1) + pos] =
                    __float2half_rn(vv[i]);
            }
        }
    }
}

__global__ __launch_bounds__(256, 1) void attn_mma_kernel(
    const float* __restrict__ q, const float* __restrict__ kv,
    float* __restrict__ x)
{
    extern __shared__ __align__(16) uint32_t smu[];
    uint32_t* sKV = smu;            // 2 x 3072
    uint32_t* sQ  = smu + 6144;     // 48 atoms x 128

    const int tid = threadIdx.x;
    const int wid = tid >> 5;
    const int lane = tid & 31;
    const int b = blockIdx.z, h = blockIdx.y;
    const int n0 = blockIdx.x * 256;
    const float qscale = 0.144337567297406441127f * 1.44269504088896340736f;

    // ---- stage Q (256 rows x 48 dims) into fp16 A-frag atoms ----
    {
        const float* qbase = q + ((size_t)(b * N_ + n0)) * C_ + h * HD_;
        #pragma unroll
        for (int it = 0; it < 12; it++) {
            int idx = tid + it * 256;
            int m = idx / 12, f4 = idx - m * 12;
            float4 v = *reinterpret_cast<const float4*>(qbase + (size_t)m * C_ + f4 * 4);
            int mi = m >> 4, lr = m & 15, g = lr & 7;
            int ki = f4 >> 2;
            int r0 = (lr >> 3) + 2 * ((f4 >> 1) & 1);
            int t0 = 2 * (f4 & 1);
            int base = (mi * 3 + ki) * 128 + r0;
            sQ[base + (g * 4 + t0) * 4]     = packh2(v.x * qscale, v.y * qscale);
            sQ[base + (g * 4 + t0 + 1) * 4] = packh2(v.z * qscale, v.w * qscale);
        }
    }
    __syncthreads();

    // ---- each warp loads 2 m-atoms x 3 k-atoms of Q fragments ----
    uint32_t qf[2][3][4];
    #pragma unroll
    for (int mi2 = 0; mi2 < 2; mi2++)
        #pragma unroll
        for (int ki = 0; ki < 3; ki++) {
            uint4 tq = *reinterpret_cast<const uint4*>(
                &sQ[((wid * 2 + mi2) * 3 + ki) * 128 + lane * 4]);
            qf[mi2][ki][0] = tq.x; qf[mi2][ki][1] = tq.y;
            qf[mi2][ki][2] = tq.z; qf[mi2][ki][3] = tq.w;
        }

    const float* kvbase = kv + ((size_t)(b * M_)) * 2 * C_ + h * HD_;
    float4 kf4[3], vf4[3];
    attn_ldg_kv(kvbase, 0, tid, kf4, vf4);
    attn_scatter_kv(sKV, tid, kf4, vf4);
    __syncthreads();   // Q frags read + buf0 staged

    float accO[2][6][4];
    #pragma unroll
    for (int mi2 = 0; mi2 < 2; mi2++)
        #pragma unroll
        for (int ni = 0; ni < 6; ni++)
            #pragma unroll
            for (int r = 0; r < 4; r++) accO[mi2][ni][r] = 0.f;
    float lp[2][2] = {{0.f, 0.f}, {0.f, 0.f}};

    for (int c = 0; c < 16; c++) {
        uint32_t* sK = sKV + (c & 1) * 3072;
        uint32_t* sV = sK + 1536;

        if (c < 15)
            attn_ldg_kv(kvbase, (c + 1) * 64, tid, kf4, vf4);

        // ---- QK^T: S[32 x 64] per warp (fp16, 3 k-steps of 16) ----
        float accS[2][8][4];
        #pragma unroll
        for (int mi2 = 0; mi2 < 2; mi2++)
            #pragma unroll
            for (int nj = 0; nj < 8; nj++)
                #pragma unroll
                for (int r = 0; r < 4; r++) accS[mi2][nj][r] = 0.f;
        #pragma unroll
        for (int nj = 0; nj < 8; nj++) {
            #pragma unroll
            for (int ki = 0; ki < 3; ki++) {
                uint2 tb = *reinterpret_cast<const uint2*>(
                    &sK[(nj * 3 + ki) * 64 + lane * 2]);
                uint32_t bf[2] = {tb.x, tb.y};
                mma_f16(accS[0][nj], qf[0][ki], bf);
                mma_f16(accS[1][nj], qf[1][ki], bf);
            }
        }

        // ---- max-free softmax -> P packed into registers (A-frag layout) ----
        uint32_t paf[2][8][2];
        #pragma unroll
        for (int mi2 = 0; mi2 < 2; mi2++) {
            float a0 = 0.f, a1 = 0.f;
            #pragma unroll
            for (int nj = 0; nj < 8; nj++) {
                float p0 = ex2(accS[mi2][nj][0]);
                float p1 = ex2(accS[mi2][nj][1]);
                float p2 = ex2(accS[mi2][nj][2]);
                float p3 = ex2(accS[mi2][nj][3]);
                a0 += p0 + p1;
                a1 += p2 + p3;
                paf[mi2][nj][0] = packh2(p0, p1);   // row g
                paf[mi2][nj][1] = packh2(p2, p3);   // row g+8
            }
            lp[mi2][0] += a0;
            lp[mi2][1] += a1;
        }

        // ---- PV: O[32 x 48] += P[32 x 64] @ V[64 x 48] (4 k-steps of 16) ----
        #pragma unroll
        for (int kk = 0; kk < 4; kk++) {
            uint32_t af[2][4];
            #pragma unroll
            for (int mi2 = 0; mi2 < 2; mi2++) {
                af[mi2][0] = paf[mi2][2 * kk][0];
                af[mi2][1] = paf[mi2][2 * kk][1];
                af[mi2][2] = paf[mi2][2 * kk + 1][0];
                af[mi2][3] = paf[mi2][2 * kk + 1][1];
            }
            #pragma unroll
            for (int ni = 0; ni < 6; ni++) {
                uint2 tb = *reinterpret_cast<const uint2*>(
                    &sV[(ni * 4 + kk) * 64 + lane * 2]);
                uint32_t bf[2] = {tb.x, tb.y};
                mma_f16(accO[0][ni], af[0], bf);
                mma_f16(accO[1][ni], af[1], bf);
            }
        }

        // ---- scatter prefetched KV into other buffer (after PV, R12 order) ----
        if (c < 15)
            attn_scatter_kv(sKV + ((c + 1) & 1) * 3072, tid, kf4, vf4);
        __syncthreads();
    }

    // ---- final l reduction (quad lanes) + normalize + store ----
    const int g = lane >> 2;
    const int t = lane & 3;
    #pragma unroll
    for (int mi2 = 0; mi2 < 2; mi2++) {
        float l0 = lp[mi2][0], l1 = lp[mi2][1];
        l0 += __shfl_xor_sync(0xffffffffu, l0, 1);
        l0 += __shfl_xor_sync(0xffffffffu, l0, 2);
        l1 += __shfl_xor_sync(0xffffffffu, l1, 1);
        l1 += __shfl_xor_sync(0xffffffffu, l1, 2);
        const float inv0 = 1.0f / l0;
        const float inv1 = 1.0f / l1;
        const int row0 = n0 + wid * 32 + mi2 * 16 + g;
        float* xp0 = x + ((size_t)(b * N_ + row0)) * C_ + h * HD_;
        float* xp1 = xp0 + (size_t)8 * C_;
        #pragma unroll
        for (int ni = 0; ni < 6; ni++) {
            *reinterpret_cast<float2*>(&xp0[ni * 8 + 2 * t]) =
                make_float2(accO[mi2][ni][0] * inv0, accO[mi2][ni][1] * inv0);
            *reinterpret_cast<float2*>(&xp1[ni * 8 + 2 * t]) =
                make_float2(accO[mi2][ni][2] * inv1, accO[mi2][ni][3] * inv1);
        }
    }
}

// ---------------------------------------------------------------------------
// Launch
// ---------------------------------------------------------------------------
extern "C" void kernel_launch(void* const* d_in, const int* in_sizes, int n_in,
                              void* d_out, int out_size)
{
    const float* q_x   = (const float*)d_in[0];  // [4,4096,384]
    const float* kv_x  = (const float*)d_in[1];  // [4,1024,384]
    const float* Wq    = (const float*)d_in[2];  // [384,384]
    const float* Wkv   = (const float*)d_in[3];  // [384,768]
    const float* Wproj = (const float*)d_in[4];  // [384,384]
    const float* bproj = (const float*)d_in[5];  // [384]
    float* out = (float*)d_out;                  // [4,4096,384]

    float *gq, *gkv, *gx, *gwqt, *gwkvt, *gwpt;
    cudaGetSymbolAddress((void**)&gq,   g_q);
    cudaGetSymbolAddress((void**)&gkv,  g_kv);
    cudaGetSymbolAddress((void**)&gx,   g_x);
    cudaGetSymbolAddress((void**)&gwqt, g_wqt);
    cudaGetSymbolAddress((void**)&gwkvt,g_wkvt);
    cudaGetSymbolAddress((void**)&gwpt, g_wpt);

    cudaFuncSetAttribute(attn_mma_kernel,
                         cudaFuncAttributeMaxDynamicSharedMemorySize,
                         ATTN_SMEM_BYTES);
    cudaFuncSetAttribute(tc_gemm12_kernel,
                         cudaFuncAttributeMaxDynamicSharedMemorySize,
                         GEMM_SMEM_BYTES);
    cudaFuncSetAttribute(tc_gemm3_kernel,
                         cudaFuncAttributeMaxDynamicSharedMemorySize,
                         GEMM_SMEM_BYTES);

    // 0) all three weight transposes in one launch
    transpose_all_kernel<<<576, dim3(32, 8)>>>(Wq, Wkv, Wproj, gwqt, gwkvt, gwpt);

    // 1+2) q and kv projections in one launch (576 flat CTAs)
    tc_gemm12_kernel<<<576, 256, GEMM_SMEM_BYTES>>>(
        q_x, gwqt, gq, kv_x, gwkvt, gkv);

    // 3) attention -> g_x [B,N,384]
    attn_mma_kernel<<<dim3(N_ / 256, H_, B_), 256, ATTN_SMEM_BYTES>>>(gq, gkv, gx);

    // 4) out = g_x @ Wproj + bproj + g_q
    tc_gemm3_kernel<<<dim3(3, 128), 256, GEMM_SMEM_BYTES>>>(
        gx, gwpt, out, bproj, gq);
}

// round 16
// speedup vs baseline: 2.0322x; 1.3552x over previous
#include <cuda_runtime.h>
#include <cuda_fp16.h>
#include <cstdint>
#include <math.h>

#define B_ 4
#define N_ 4096
#define M_ 1024
#define C_ 384
#define H_ 8
#define HD_ 48
#define KDIM 384

// ---------------------------------------------------------------------------
// Scratch (allocation-free rule: __device__ globals)
// ---------------------------------------------------------------------------
__device__ float g_q  [B_ * (size_t)N_ * C_];      // q projection  [B,N,384]
__device__ float g_kv [B_ * (size_t)M_ * 2 * C_];  // kv projection [B,M,2,384]
__device__ float g_x  [B_ * (size_t)N_ * C_];      // attention out [B,N,384]
__device__ __half g_wqt [C_ * C_];                 // Wq^T  fp16 [384][384]
__device__ __half g_wkvt[2 * C_ * C_];             // Wkv^T fp16 [768][384]
__device__ __half g_wpt [C_ * C_];                 // Wproj^T fp16 [384][384]

// ---------------------------------------------------------------------------
// helpers
// ---------------------------------------------------------------------------
__device__ __forceinline__ float ex2(float x) {
    float y;
    asm("ex2.approx.ftz.f32 %0, %1;" : "=f"(y) : "f"(x));
    return y;
}
__device__ __forceinline__ uint32_t packh2(float lo, float hi) {
    __half2 h = __floats2half2_rn(lo, hi);
    return *reinterpret_cast<uint32_t*>(&h);
}
// fp16: D(16x8) += A(16x16) * B(16x8), fp32 accumulate (HW-verified R14)
__device__ __forceinline__ void mma_f16(float* d, const uint32_t* a, const uint32_t* b) {
    asm volatile("mma.sync.aligned.m16n8k16.row.col.f32.f16.f16.f32 "
                 "{%0,%1,%2,%3}, {%4,%5,%6,%7}, {%8,%9}, {%0,%1,%2,%3};"
                 : "+f"(d[0]), "+f"(d[1]), "+f"(d[2]), "+f"(d[3])
                 : "r"(a[0]), "r"(a[1]), "r"(a[2]), "r"(a[3]),
                   "r"(b[0]), "r"(b[1]));
}

// ---------------------------------------------------------------------------
// Fused weight transposes + fp16 conversion (one launch).
// out[n][k] = fp16(in[k][n])
// ---------------------------------------------------------------------------
__global__ void transpose_all_kernel(const float* __restrict__ Wq,
                                     const float* __restrict__ Wkv,
                                     const float* __restrict__ Wp,
                                     __half* __restrict__ oq,
                                     __half* __restrict__ okv,
                                     __half* __restrict__ op)
{
    __shared__ float tbuf[32][33];
    const int bid = blockIdx.x;
    const float* in; __half* out; int Ncols, tile;
    if (bid < 144)      { in = Wq;  out = oq;  Ncols = 384; tile = bid; }
    else if (bid < 432) { in = Wkv; out = okv; Ncols = 768; tile = bid - 144; }
    else                { in = Wp;  out = op;  Ncols = 384; tile = bid - 432; }
    const int tilesX = Ncols / 32;
    const int n0 = (tile % tilesX) * 32;
    const int k0 = (tile / tilesX) * 32;
    const int x = threadIdx.x, y = threadIdx.y;
    #pragma unroll
    for (int i = 0; i < 32; i += 8)
        tbuf[y + i][x] = in[(size_t)(k0 + y + i) * Ncols + n0 + x];
    __syncthreads();
    #pragma unroll
    for (int i = 0; i < 32; i += 8)
        out[(size_t)(n0 + y + i) * KDIM + k0 + x] = __float2half_rn(tbuf[x][y + i]);
}

// ---------------------------------------------------------------------------
// FP16 tensor-core GEMM: C[M,Ncols] = A[M,384] @ WT[Ncols,384]^T
//                        (+ bias + res if EPI)
// Structurally identical to attention's S = Q K^T (HW-verified layouts):
//   A staged like Q (A-frag atoms, 2 k-atoms per 32k chunk),
//   WT staged like K (B-frag atoms).
// 128x128 tile/CTA, BK=32 (2 fp16 k-steps), 8 warps (4m x 2n), 2-stage pipe.
// Smem: 2 buffers x (sA 2048 + sB 2048 u32) = 32 KB.
// ---------------------------------------------------------------------------
#define GEMM_SMEM_BYTES (2 * 4096 * 4)

template <bool EPI>
__device__ __forceinline__ void gemm_body(
    const float* __restrict__ A, const __half* __restrict__ WT,
    float* __restrict__ C, int Ncols, int rowBase, int colBase,
    const float* __restrict__ bias, const float* __restrict__ res,
    uint32_t* sm_g)
{
    const int tid = threadIdx.x;
    const int wid = tid >> 5;
    const int lane = tid & 31;
    const int warpM = wid >> 1;
    const int warpN = wid & 1;

    // staging geometry (constant per thread): m/n = tid>>3 (+32/it), f4 = tid&7
    const int f4 = tid & 7;
    const int rRow = tid >> 3;              // 0..31
    const int ki_s = f4 >> 2;               // k-atom within chunk
    const int lrA = rRow & 15;
    const int gA = lrA & 7;
    const int r0A = (lrA >> 3) + 2 * ((f4 >> 1) & 1);
    const int slotA = (gA * 4 + 2 * (f4 & 1)) * 4;
    const int gB = rRow & 7;
    const int jB = (f4 >> 1) & 1;
    const int slotB = (gB * 4 + 2 * (f4 & 1)) * 2;
    int baseA[4], baseB[4];
    #pragma unroll
    for (int it = 0; it < 4; it++) {
        int m = rRow + it * 32;
        baseA[it] = ((m >> 4) * 2 + ki_s) * 128 + r0A;          // + slotA, +4
        baseB[it] = ((m >> 3) * 2 + ki_s) * 64 + jB;            // + slotB, +2
    }
    const float* Ap = A + (size_t)(rowBase + rRow) * KDIM + f4 * 4;
    const uint32_t* Wp32 = reinterpret_cast<const uint32_t*>(WT) +
                           ((size_t)(colBase + rRow) * KDIM >> 1) + f4 * 2;

    float4 aReg[4];
    uint2 bReg[4];
    #pragma unroll
    for (int it = 0; it < 4; it++) {
        aReg[it] = *reinterpret_cast<const float4*>(Ap + (size_t)it * 32 * KDIM);
        bReg[it] = *reinterpret_cast<const uint2*>(Wp32 + (size_t)it * 16 * KDIM);
    }
    {
        uint32_t* sA = sm_g;
        uint32_t* sB = sm_g + 2048;
        #pragma unroll
        for (int it = 0; it < 4; it++) {
            sA[baseA[it] + slotA]     = packh2(aReg[it].x, aReg[it].y);
            sA[baseA[it] + slotA + 4] = packh2(aReg[it].z, aReg[it].w);
            sB[baseB[it] + slotB]     = bReg[it].x;
            sB[baseB[it] + slotB + 2] = bReg[it].y;
        }
    }
    __syncthreads();

    float acc[2][8][4];
    #pragma unroll
    for (int i = 0; i < 2; i++)
        #pragma unroll
        for (int j = 0; j < 8; j++)
            #pragma unroll
            for (int r = 0; r < 4; r++) acc[i][j][r] = 0.f;

    for (int c = 0; c < 12; c++) {
        uint32_t* sA = sm_g + (c & 1) * 4096;
        uint32_t* sB = sA + 2048;

        if (c < 11) {   // prefetch next chunk (latency hidden behind MMAs)
            const int k0 = (c + 1) * 32;
            #pragma unroll
            for (int it = 0; it < 4; it++) {
                aReg[it] = *reinterpret_cast<const float4*>(
                    Ap + (size_t)it * 32 * KDIM + k0);
                bReg[it] = *reinterpret_cast<const uint2*>(
                    Wp32 + (size_t)it * 16 * KDIM + (k0 >> 1));
            }
        }

        #pragma unroll
        for (int ki = 0; ki < 2; ki++) {
            uint32_t af[2][4];
            #pragma unroll
            for (int mi2 = 0; mi2 < 2; mi2++) {
                uint4 t = *reinterpret_cast<const uint4*>(
                    &sA[((warpM * 2 + mi2) * 2 + ki) * 128 + lane * 4]);
                af[mi2][0] = t.x; af[mi2][1] = t.y;
                af[mi2][2] = t.z; af[mi2][3] = t.w;
            }
            #pragma unroll
            for (int nj = 0; nj < 8; nj++) {
                uint2 t = *reinterpret_cast<const uint2*>(
                    &sB[((warpN * 8 + nj) * 2 + ki) * 64 + lane * 2]);
                uint32_t bf[2] = {t.x, t.y};
                mma_f16(acc[0][nj], af[0], bf);
                mma_f16(acc[1][nj], af[1], bf);
            }
        }

        if (c < 11) {   // scatter prefetched regs into other buffer
            uint32_t* dA = sm_g + ((c + 1) & 1) * 4096;
            uint32_t* dB = dA + 2048;
            #pragma unroll
            for (int it = 0; it < 4; it++) {
                dA[baseA[it] + slotA]     = packh2(aReg[it].x, aReg[it].y);
                dA[baseA[it] + slotA + 4] = packh2(aReg[it].z, aReg[it].w);
                dB[baseB[it] + slotB]     = bReg[it].x;
                dB[baseB[it] + slotB + 2] = bReg[it].y;
            }
        }
        __syncthreads();
    }

    const int groupID = lane >> 2;
    const int tig = lane & 3;
    #pragma unroll
    for (int mi2 = 0; mi2 < 2; mi2++) {
        const int row0 = rowBase + warpM * 32 + mi2 * 16 + groupID;
        #pragma unroll
        for (int nj = 0; nj < 8; nj++) {
            const int col = colBase + warpN * 64 + nj * 8 + tig * 2;
            float2 lo = make_float2(acc[mi2][nj][0], acc[mi2][nj][1]);
            float2 hi = make_float2(acc[mi2][nj][2], acc[mi2][nj][3]);
            if (EPI) {
                float2 bz = *reinterpret_cast<const float2*>(&bias[col]);
                float2 r0 = *reinterpret_cast<const float2*>(
                    &res[(size_t)row0 * Ncols + col]);
                float2 r1 = *reinterpret_cast<const float2*>(
                    &res[(size_t)(row0 + 8) * Ncols + col]);
                lo.x += bz.x + r0.x; lo.y += bz.y + r0.y;
                hi.x += bz.x + r1.x; hi.y += bz.y + r1.y;
            }
            *reinterpret_cast<float2*>(&C[(size_t)row0 * Ncols + col]) = lo;
            *reinterpret_cast<float2*>(&C[(size_t)(row0 + 8) * Ncols + col]) = hi;
        }
    }
}

// gemm1 + gemm2 in ONE launch: 384 + 192 = 576 flat CTAs.
__global__ __launch_bounds__(256) void tc_gemm12_kernel(
    const float* __restrict__ A1, const __half* __restrict__ BT1, float* __restrict__ C1,
    const float* __restrict__ A2, const __half* __restrict__ BT2, float* __restrict__ C2)
{
    extern __shared__ __align__(16) uint32_t sm_g[];
    const int bid = blockIdx.x;
    if (bid < 384) {
        gemm_body<false>(A1, BT1, C1, C_, (bid / 3) * 128, (bid % 3) * 128,
                         nullptr, nullptr, sm_g);
    } else {
        const int t = bid - 384;
        gemm_body<false>(A2, BT2, C2, 2 * C_, (t / 6) * 128, (t % 6) * 128,
                         nullptr, nullptr, sm_g);
    }
}

__global__ __launch_bounds__(256) void tc_gemm3_kernel(
    const float* __restrict__ A, const __half* __restrict__ BT, float* __restrict__ C,
    const float* __restrict__ bias, const float* __restrict__ res)
{
    extern __shared__ __align__(16) uint32_t sm_g[];
    gemm_body<true>(A, BT, C, C_, (int)blockIdx.y * 128, (int)blockIdx.x * 128,
                    bias, res, sm_g);
}

// ---------------------------------------------------------------------------
// FP16 tensor-core flash attention, register-resident P (HW-verified R14).
// ---------------------------------------------------------------------------
#define ATTN_SMEM_BYTES (12288 * 4)

__device__ __forceinline__ void attn_ldg_kv(
    const float* __restrict__ kvbase, int m0, int tid,
    float4* kf4, float4* vf4)
{
    #pragma unroll
    for (int it = 0; it < 3; it++) {
        int idx = tid + it * 256;
        int n = idx / 12, f4 = idx - n * 12;
        const float* p = kvbase + (size_t)(m0 + n) * 2 * C_ + f4 * 4;
        kf4[it] = *reinterpret_cast<const float4*>(p);
        vf4[it] = *reinterpret_cast<const float4*>(p + C_);
    }
}

__device__ __forceinline__ void attn_scatter_kv(
    uint32_t* __restrict__ sKb, int tid, const float4* kf4, const float4* vf4)
{
    __half* sVh = reinterpret_cast<__half*>(sKb + 1536);
    #pragma unroll
    for (int it = 0; it < 3; it++) {
        int idx = tid + it * 256;
        int n = idx / 12, f4 = idx - n * 12;
        {
            int nj = n >> 3, g = n & 7, ki = f4 >> 2;
            int j = (f4 >> 1) & 1, t0 = 2 * (f4 & 1);
            int kb = (nj * 3 + ki) * 64 + j;
            sKb[kb + (g * 4 + t0) * 2]     = packh2(kf4[it].x, kf4[it].y);
            sKb[kb + (g * 4 + t0 + 1) * 2] = packh2(kf4[it].z, kf4[it].w);
        }
        {
            int kv = n >> 4, lk = n & 15;
            int jv = lk >> 3, tv = (lk & 7) >> 1, pos = lk & 1;
            float vv[4] = {vf4[it].x, vf4[it].y, vf4[it].z, vf4[it].w};
            #pragma unroll
            for (int i = 0; i < 4; i++) {
                int d = 4 * f4 + i;
                int ni = d >> 3, gd = d & 7;
                sVh[(((ni * 4 + kv) * 64 + (gd * 4 + tv) * 2 + jv) << 1) + pos] =
                    __float2half_rn(vv[i]);
            }
        }
    }
}

__global__ __launch_bounds__(256, 1) void attn_mma_kernel(
    const float* __restrict__ q, const float* __restrict__ kv,
    float* __restrict__ x)
{
    extern __shared__ __align__(16) uint32_t smu[];
    uint32_t* sKV = smu;            // 2 x 3072
    uint32_t* sQ  = smu + 6144;     // 48 atoms x 128

    const int tid = threadIdx.x;
    const int wid = tid >> 5;
    const int lane = tid & 31;
    const int b = blockIdx.z, h = blockIdx.y;
    const int n0 = blockIdx.x * 256;
    const float qscale = 0.144337567297406441127f * 1.44269504088896340736f;

    {
        const float* qbase = q + ((size_t)(b * N_ + n0)) * C_ + h * HD_;
        #pragma unroll
        for (int it = 0; it < 12; it++) {
            int idx = tid + it * 256;
            int m = idx / 12, f4 = idx - m * 12;
            float4 v = *reinterpret_cast<const float4*>(qbase + (size_t)m * C_ + f4 * 4);
            int mi = m >> 4, lr = m & 15, g = lr & 7;
            int ki = f4 >> 2;
            int r0 = (lr >> 3) + 2 * ((f4 >> 1) & 1);
            int t0 = 2 * (f4 & 1);
            int base = (mi * 3 + ki) * 128 + r0;
            sQ[base + (g * 4 + t0) * 4]     = packh2(v.x * qscale, v.y * qscale);
            sQ[base + (g * 4 + t0 + 1) * 4] = packh2(v.z * qscale, v.w * qscale);
        }
    }
    __syncthreads();

    uint32_t qf[2][3][4];
    #pragma unroll
    for (int mi2 = 0; mi2 < 2; mi2++)
        #pragma unroll
        for (int ki = 0; ki < 3; ki++) {
            uint4 tq = *reinterpret_cast<const uint4*>(
                &sQ[((wid * 2 + mi2) * 3 + ki) * 128 + lane * 4]);
            qf[mi2][ki][0] = tq.x; qf[mi2][ki][1] = tq.y;
            qf[mi2][ki][2] = tq.z; qf[mi2][ki][3] = tq.w;
        }

    const float* kvbase = kv + ((size_t)(b * M_)) * 2 * C_ + h * HD_;
    float4 kf4[3], vf4[3];
    attn_ldg_kv(kvbase, 0, tid, kf4, vf4);
    attn_scatter_kv(sKV, tid, kf4, vf4);
    __syncthreads();

    float accO[2][6][4];
    #pragma unroll
    for (int mi2 = 0; mi2 < 2; mi2++)
        #pragma unroll
        for (int ni = 0; ni < 6; ni++)
            #pragma unroll
            for (int r = 0; r < 4; r++) accO[mi2][ni][r] = 0.f;
    float lp[2][2] = {{0.f, 0.f}, {0.f, 0.f}};

    for (int c = 0; c < 16; c++) {
        uint32_t* sK = sKV + (c & 1) * 3072;
        uint32_t* sV = sK + 1536;

        if (c < 15)
            attn_ldg_kv(kvbase, (c + 1) * 64, tid, kf4, vf4);

        float accS[2][8][4];
        #pragma unroll
        for (int mi2 = 0; mi2 < 2; mi2++)
            #pragma unroll
            for (int nj = 0; nj < 8; nj++)
                #pragma unroll
                for (int r = 0; r < 4; r++) accS[mi2][nj][r] = 0.f;
        #pragma unroll
        for (int nj = 0; nj < 8; nj++) {
            #pragma unroll
            for (int ki = 0; ki < 3; ki++) {
                uint2 tb = *reinterpret_cast<const uint2*>(
                    &sK[(nj * 3 + ki) * 64 + lane * 2]);
                uint32_t bf[2] = {tb.x, tb.y};
                mma_f16(accS[0][nj], qf[0][ki], bf);
                mma_f16(accS[1][nj], qf[1][ki], bf);
            }
        }

        uint32_t paf[2][8][2];
        #pragma unroll
        for (int mi2 = 0; mi2 < 2; mi2++) {
            float a0 = 0.f, a1 = 0.f;
            #pragma unroll
            for (int nj = 0; nj < 8; nj++) {
                float p0 = ex2(accS[mi2][nj][0]);
                float p1 = ex2(accS[mi2][nj][1]);
                float p2 = ex2(accS[mi2][nj][2]);
                float p3 = ex2(accS[mi2][nj][3]);
                a0 += p0 + p1;
                a1 += p2 + p3;
                paf[mi2][nj][0] = packh2(p0, p1);
                paf[mi2][nj][1] = packh2(p2, p3);
            }
            lp[mi2][0] += a0;
            lp[mi2][1] += a1;
        }

        #pragma unroll
        for (int kk = 0; kk < 4; kk++) {
            uint32_t af[2][4];
            #pragma unroll
            for (int mi2 = 0; mi2 < 2; mi2++) {
                af[mi2][0] = paf[mi2][2 * kk][0];
                af[mi2][1] = paf[mi2][2 * kk][1];
                af[mi2][2] = paf[mi2][2 * kk + 1][0];
                af[mi2][3] = paf[mi2][2 * kk + 1][1];
            }
            #pragma unroll
            for (int ni = 0; ni < 6; ni++) {
                uint2 tb = *reinterpret_cast<const uint2*>(
                    &sV[(ni * 4 + kk) * 64 + lane * 2]);
                uint32_t bf[2] = {tb.x, tb.y};
                mma_f16(accO[0][ni], af[0], bf);
                mma_f16(accO[1][ni], af[1], bf);
            }
        }

        if (c < 15)
            attn_scatter_kv(sKV + ((c + 1) & 1) * 3072, tid, kf4, vf4);
        __syncthreads();
    }

    const int g = lane >> 2;
    const int t = lane & 3;
    #pragma unroll
    for (int mi2 = 0; mi2 < 2; mi2++) {
        float l0 = lp[mi2][0], l1 = lp[mi2][1];
        l0 += __shfl_xor_sync(0xffffffffu, l0, 1);
        l0 += __shfl_xor_sync(0xffffffffu, l0, 2);
        l1 += __shfl_xor_sync(0xffffffffu, l1, 1);
        l1 += __shfl_xor_sync(0xffffffffu, l1, 2);
        const float inv0 = 1.0f / l0;
        const float inv1 = 1.0f / l1;
        const int row0 = n0 + wid * 32 + mi2 * 16 + g;
        float* xp0 = x + ((size_t)(b * N_ + row0)) * C_ + h * HD_;
        float* xp1 = xp0 + (size_t)8 * C_;
        #pragma unroll
        for (int ni = 0; ni < 6; ni++) {
            *reinterpret_cast<float2*>(&xp0[ni * 8 + 2 * t]) =
                make_float2(accO[mi2][ni][0] * inv0, accO[mi2][ni][1] * inv0);
            *reinterpret_cast<float2*>(&xp1[ni * 8 + 2 * t]) =
                make_float2(accO[mi2][ni][2] * inv1, accO[mi2][ni][3] * inv1);
        }
    }
}

// ---------------------------------------------------------------------------
// Launch
// ---------------------------------------------------------------------------
extern "C" void kernel_launch(void* const* d_in, const int* in_sizes, int n_in,
                              void* d_out, int out_size)
{
    const float* q_x   = (const float*)d_in[0];  // [4,4096,384]
    const float* kv_x  = (const float*)d_in[1];  // [4,1024,384]
    const float* Wq    = (const float*)d_in[2];  // [384,384]
    const float* Wkv   = (const float*)d_in[3];  // [384,768]
    const float* Wproj = (const float*)d_in[4];  // [384,384]
    const float* bproj = (const float*)d_in[5];  // [384]
    float* out = (float*)d_out;                  // [4,4096,384]

    float *gq, *gkv, *gx;
    __half *gwqt, *gwkvt, *gwpt;
    cudaGetSymbolAddress((void**)&gq,   g_q);
    cudaGetSymbolAddress((void**)&gkv,  g_kv);
    cudaGetSymbolAddress((void**)&gx,   g_x);
    cudaGetSymbolAddress((void**)&gwqt, g_wqt);
    cudaGetSymbolAddress((void**)&gwkvt,g_wkvt);
    cudaGetSymbolAddress((void**)&gwpt, g_wpt);

    cudaFuncSetAttribute(attn_mma_kernel,
                         cudaFuncAttributeMaxDynamicSharedMemorySize,
                         ATTN_SMEM_BYTES);
    cudaFuncSetAttribute(tc_gemm12_kernel,
                         cudaFuncAttributeMaxDynamicSharedMemorySize,
                         GEMM_SMEM_BYTES);
    cudaFuncSetAttribute(tc_gemm3_kernel,
                         cudaFuncAttributeMaxDynamicSharedMemorySize,
                         GEMM_SMEM_BYTES);

    // 0) all three weight transposes + fp16 conversion in one launch
    transpose_all_kernel<<<576, dim3(32, 8)>>>(Wq, Wkv, Wproj, gwqt, gwkvt, gwpt);

    // 1+2) q and kv projections in one launch (576 flat CTAs)
    tc_gemm12_kernel<<<576, 256, GEMM_SMEM_BYTES>>>(
        q_x, gwqt, gq, kv_x, gwkvt, gkv);

    // 3) attention -> g_x [B,N,384]
    attn_mma_kernel<<<dim3(N_ / 256, H_, B_), 256, ATTN_SMEM_BYTES>>>(gq, gkv, gx);

    // 4) out = g_x @ Wproj + bproj + g_q
    tc_gemm3_kernel<<<dim3(3, 128), 256, GEMM_SMEM_BYTES>>>(
        gx, gwpt, out, bproj, gq);
}

// round 17
// speedup vs baseline: 2.1255x; 1.0459x over previous
#include <cuda_runtime.h>
#include <cuda_fp16.h>
#include <cstdint>
#include <math.h>

#define B_ 4
#define N_ 4096
#define M_ 1024
#define C_ 384
#define H_ 8
#define HD_ 48
#define KDIM 384

// ---------------------------------------------------------------------------
// Scratch (allocation-free rule: __device__ globals)
// ---------------------------------------------------------------------------
__device__ float g_q  [B_ * (size_t)N_ * C_];      // q projection  [B,N,384]
__device__ float g_kv [B_ * (size_t)M_ * 2 * C_];  // kv projection [B,M,2,384]
// attention out as fp16 A-fragment blob: [rowblk(1024)][atom(24)][128 u32]
__device__ uint32_t g_xf[(size_t)(B_ * N_ / 16) * 24 * 128];
__device__ __half g_wqt [C_ * C_];                 // Wq^T  fp16
__device__ __half g_wkvt[2 * C_ * C_];             // Wkv^T fp16
__device__ __half g_wpt [C_ * C_];                 // Wproj^T fp16

// ---------------------------------------------------------------------------
// helpers
// ---------------------------------------------------------------------------
__device__ __forceinline__ uint32_t packh2(float lo, float hi) {
    __half2 h = __floats2half2_rn(lo, hi);
    return *reinterpret_cast<uint32_t*>(&h);
}
__device__ __forceinline__ uint32_t ex2h2(uint32_t x) {   // 2 half exps, 1 MUFU op
    uint32_t y;
    asm("ex2.approx.f16x2 %0, %1;" : "=r"(y) : "r"(x));
    return y;
}
// fp16: D(16x8) += A(16x16) * B(16x8), fp32 accumulate (HW-verified)
__device__ __forceinline__ void mma_f16(float* d, const uint32_t* a, const uint32_t* b) {
    asm volatile("mma.sync.aligned.m16n8k16.row.col.f32.f16.f16.f32 "
                 "{%0,%1,%2,%3}, {%4,%5,%6,%7}, {%8,%9}, {%0,%1,%2,%3};"
                 : "+f"(d[0]), "+f"(d[1]), "+f"(d[2]), "+f"(d[3])
                 : "r"(a[0]), "r"(a[1]), "r"(a[2]), "r"(a[3]),
                   "r"(b[0]), "r"(b[1]));
}

// ---------------------------------------------------------------------------
// Fused weight transposes + fp16 conversion (one launch).
// ---------------------------------------------------------------------------
__global__ void transpose_all_kernel(const float* __restrict__ Wq,
                                     const float* __restrict__ Wkv,
                                     const float* __restrict__ Wp,
                                     __half* __restrict__ oq,
                                     __half* __restrict__ okv,
                                     __half* __restrict__ op)
{
    __shared__ float tbuf[32][33];
    const int bid = blockIdx.x;
    const float* in; __half* out; int Ncols, tile;
    if (bid < 144)      { in = Wq;  out = oq;  Ncols = 384; tile = bid; }
    else if (bid < 432) { in = Wkv; out = okv; Ncols = 768; tile = bid - 144; }
    else                { in = Wp;  out = op;  Ncols = 384; tile = bid - 432; }
    const int tilesX = Ncols / 32;
    const int n0 = (tile % tilesX) * 32;
    const int k0 = (tile / tilesX) * 32;
    const int x = threadIdx.x, y = threadIdx.y;
    #pragma unroll
    for (int i = 0; i < 32; i += 8)
        tbuf[y + i][x] = in[(size_t)(k0 + y + i) * Ncols + n0 + x];
    __syncthreads();
    #pragma unroll
    for (int i = 0; i < 32; i += 8)
        out[(size_t)(n0 + y + i) * KDIM + k0 + x] = __float2half_rn(tbuf[x][y + i]);
}

// ---------------------------------------------------------------------------
// FP16 tensor-core GEMM body (fp32 A staged->fp16 frags), 2-stage pipelined.
// Used by gemm1+gemm2. (HW-verified R16.)
// ---------------------------------------------------------------------------
#define GEMM_SMEM_BYTES (2 * 4096 * 4)

__device__ __forceinline__ void gemm_body(
    const float* __restrict__ A, const __half* __restrict__ WT,
    float* __restrict__ C, int Ncols, int rowBase, int colBase,
    uint32_t* sm_g)
{
    const int tid = threadIdx.x;
    const int wid = tid >> 5;
    const int lane = tid & 31;
    const int warpM = wid >> 1;
    const int warpN = wid & 1;

    const int f4 = tid & 7;
    const int rRow = tid >> 3;
    const int ki_s = f4 >> 2;
    const int lrA = rRow & 15;
    const int gA = lrA & 7;
    const int r0A = (lrA >> 3) + 2 * ((f4 >> 1) & 1);
    const int slotA = (gA * 4 + 2 * (f4 & 1)) * 4;
    const int gB = rRow & 7;
    const int jB = (f4 >> 1) & 1;
    const int slotB = (gB * 4 + 2 * (f4 & 1)) * 2;
    int baseA[4], baseB[4];
    #pragma unroll
    for (int it = 0; it < 4; it++) {
        int m = rRow + it * 32;
        baseA[it] = ((m >> 4) * 2 + ki_s) * 128 + r0A;
        baseB[it] = ((m >> 3) * 2 + ki_s) * 64 + jB;
    }
    const float* Ap = A + (size_t)(rowBase + rRow) * KDIM + f4 * 4;
    const uint32_t* Wp32 = reinterpret_cast<const uint32_t*>(WT) +
                           ((size_t)(colBase + rRow) * KDIM >> 1) + f4 * 2;

    float4 aReg[4];
    uint2 bReg[4];
    #pragma unroll
    for (int it = 0; it < 4; it++) {
        aReg[it] = *reinterpret_cast<const float4*>(Ap + (size_t)it * 32 * KDIM);
        bReg[it] = *reinterpret_cast<const uint2*>(Wp32 + (size_t)it * 16 * KDIM);
    }
    {
        uint32_t* sA = sm_g;
        uint32_t* sB = sm_g + 2048;
        #pragma unroll
        for (int it = 0; it < 4; it++) {
            sA[baseA[it] + slotA]     = packh2(aReg[it].x, aReg[it].y);
            sA[baseA[it] + slotA + 4] = packh2(aReg[it].z, aReg[it].w);
            sB[baseB[it] + slotB]     = bReg[it].x;
            sB[baseB[it] + slotB + 2] = bReg[it].y;
        }
    }
    __syncthreads();

    float acc[2][8][4];
    #pragma unroll
    for (int i = 0; i < 2; i++)
        #pragma unroll
        for (int j = 0; j < 8; j++)
            #pragma unroll
            for (int r = 0; r < 4; r++) acc[i][j][r] = 0.f;

    for (int c = 0; c < 12; c++) {
        uint32_t* sA = sm_g + (c & 1) * 4096;
        uint32_t* sB = sA + 2048;

        if (c < 11) {
            const int k0 = (c + 1) * 32;
            #pragma unroll
            for (int it = 0; it < 4; it++) {
                aReg[it] = *reinterpret_cast<const float4*>(
                    Ap + (size_t)it * 32 * KDIM + k0);
                bReg[it] = *reinterpret_cast<const uint2*>(
                    Wp32 + (size_t)it * 16 * KDIM + (k0 >> 1));
            }
        }

        #pragma unroll
        for (int ki = 0; ki < 2; ki++) {
            uint32_t af[2][4];
            #pragma unroll
            for (int mi2 = 0; mi2 < 2; mi2++) {
                uint4 t = *reinterpret_cast<const uint4*>(
                    &sA[((warpM * 2 + mi2) * 2 + ki) * 128 + lane * 4]);
                af[mi2][0] = t.x; af[mi2][1] = t.y;
                af[mi2][2] = t.z; af[mi2][3] = t.w;
            }
            #pragma unroll
            for (int nj = 0; nj < 8; nj++) {
                uint2 t = *reinterpret_cast<const uint2*>(
                    &sB[((warpN * 8 + nj) * 2 + ki) * 64 + lane * 2]);
                uint32_t bf[2] = {t.x, t.y};
                mma_f16(acc[0][nj], af[0], bf);
                mma_f16(acc[1][nj], af[1], bf);
            }
        }

        if (c < 11) {
            uint32_t* dA = sm_g + ((c + 1) & 1) * 4096;
            uint32_t* dB = dA + 2048;
            #pragma unroll
            for (int it = 0; it < 4; it++) {
                dA[baseA[it] + slotA]     = packh2(aReg[it].x, aReg[it].y);
                dA[baseA[it] + slotA + 4] = packh2(aReg[it].z, aReg[it].w);
                dB[baseB[it] + slotB]     = bReg[it].x;
                dB[baseB[it] + slotB + 2] = bReg[it].y;
            }
        }
        __syncthreads();
    }

    const int groupID = lane >> 2;
    const int tig = lane & 3;
    #pragma unroll
    for (int mi2 = 0; mi2 < 2; mi2++) {
        const int row0 = rowBase + warpM * 32 + mi2 * 16 + groupID;
        #pragma unroll
        for (int nj = 0; nj < 8; nj++) {
            const int col = colBase + warpN * 64 + nj * 8 + tig * 2;
            *reinterpret_cast<float2*>(&C[(size_t)row0 * Ncols + col]) =
                make_float2(acc[mi2][nj][0], acc[mi2][nj][1]);
            *reinterpret_cast<float2*>(&C[(size_t)(row0 + 8) * Ncols + col]) =
                make_float2(acc[mi2][nj][2], acc[mi2][nj][3]);
        }
    }
}

// gemm1 + gemm2 in ONE launch: 384 + 192 = 576 flat CTAs.
__global__ __launch_bounds__(256) void tc_gemm12_kernel(
    const float* __restrict__ A1, const __half* __restrict__ BT1, float* __restrict__ C1,
    const float* __restrict__ A2, const __half* __restrict__ BT2, float* __restrict__ C2)
{
    extern __shared__ __align__(16) uint32_t sm_g[];
    const int bid = blockIdx.x;
    if (bid < 384) {
        gemm_body(A1, BT1, C1, C_, (bid / 3) * 128, (bid % 3) * 128, sm_g);
    } else {
        const int t = bid - 384;
        gemm_body(A2, BT2, C2, 2 * C_, (t / 6) * 128, (t % 6) * 128, sm_g);
    }
}

// ---------------------------------------------------------------------------
// gemm3: out = xf_blob @ Wproj^T + bias + residual.
// A comes pre-shuffled as fp16 fragment atoms in gmem (written by attention):
// each warp LDG.128s its own fragments directly — NO A smem, NO A staging.
// Only B (weights) is staged/double-buffered: 16 KB static smem.
// ---------------------------------------------------------------------------
__global__ __launch_bounds__(256) void tc_gemm3_kernel(
    const uint32_t* __restrict__ AF, const __half* __restrict__ BT,
    float* __restrict__ C,
    const float* __restrict__ bias, const float* __restrict__ res)
{
    __shared__ __align__(16) uint32_t sB2[2][2048];

    const int tid = threadIdx.x;
    const int wid = tid >> 5;
    const int lane = tid & 31;
    const int warpM = wid >> 1;
    const int warpN = wid & 1;
    const int rowBase = blockIdx.y * 128;
    const int colBase = blockIdx.x * 128;

    // B staging geometry (same scheme as gemm_body's B)
    const int f4 = tid & 7;
    const int rRow = tid >> 3;
    const int ki_s = f4 >> 2;
    const int gB = rRow & 7;
    const int jB = (f4 >> 1) & 1;
    const int slotB = (gB * 4 + 2 * (f4 & 1)) * 2;
    int baseB[4];
    #pragma unroll
    for (int it = 0; it < 4; it++) {
        int m = rRow + it * 32;
        baseB[it] = ((m >> 3) * 2 + ki_s) * 64 + jB;
    }
    const uint32_t* Wp32 = reinterpret_cast<const uint32_t*>(BT) +
                           ((size_t)(colBase + rRow) * KDIM >> 1) + f4 * 2;

    // A fragment pointers: per warp, 2 m-atoms; blob [rowblk][atom 24][128]
    const uint32_t* afp[2];
    #pragma unroll
    for (int mi2 = 0; mi2 < 2; mi2++)
        afp[mi2] = AF + ((size_t)((rowBase + warpM * 32 + mi2 * 16) >> 4) * 24) * 128
                      + lane * 4;

    uint2 bReg[4];
    #pragma unroll
    for (int it = 0; it < 4; it++)
        bReg[it] = *reinterpret_cast<const uint2*>(Wp32 + (size_t)it * 16 * KDIM);
    uint4 afCur[2][2];
    #pragma unroll
    for (int mi2 = 0; mi2 < 2; mi2++)
        #pragma unroll
        for (int ki = 0; ki < 2; ki++)
            afCur[mi2][ki] = *reinterpret_cast<const uint4*>(afp[mi2] + ki * 128);
    #pragma unroll
    for (int it = 0; it < 4; it++) {
        sB2[0][baseB[it] + slotB]     = bReg[it].x;
        sB2[0][baseB[it] + slotB + 2] = bReg[it].y;
    }
    __syncthreads();

    float acc[2][8][4];
    #pragma unroll
    for (int i = 0; i < 2; i++)
        #pragma unroll
        for (int j = 0; j < 8; j++)
            #pragma unroll
            for (int r = 0; r < 4; r++) acc[i][j][r] = 0.f;

    for (int c = 0; c < 12; c++) {
        uint32_t* sB = sB2[c & 1];
        uint4 afNext[2][2];

        if (c < 11) {
            const int k16 = (c + 1) * 16;
            #pragma unroll
            for (int it = 0; it < 4; it++)
                bReg[it] = *reinterpret_cast<const uint2*>(
                    Wp32 + (size_t)it * 16 * KDIM + k16);
            #pragma unroll
            for (int mi2 = 0; mi2 < 2; mi2++)
                #pragma unroll
                for (int ki = 0; ki < 2; ki++)
                    afNext[mi2][ki] = *reinterpret_cast<const uint4*>(
                        afp[mi2] + ((c + 1) * 2 + ki) * 128);
        }

        #pragma unroll
        for (int ki = 0; ki < 2; ki++) {
            #pragma unroll
            for (int nj = 0; nj < 8; nj++) {
                uint2 t = *reinterpret_cast<const uint2*>(
                    &sB[((warpN * 8 + nj) * 2 + ki) * 64 + lane * 2]);
                uint32_t bf[2] = {t.x, t.y};
                mma_f16(acc[0][nj], reinterpret_cast<uint32_t*>(&afCur[0][ki]), bf);
                mma_f16(acc[1][nj], reinterpret_cast<uint32_t*>(&afCur[1][ki]), bf);
            }
        }

        if (c < 11) {
            uint32_t* dB = sB2[(c + 1) & 1];
            #pragma unroll
            for (int it = 0; it < 4; it++) {
                dB[baseB[it] + slotB]     = bReg[it].x;
                dB[baseB[it] + slotB + 2] = bReg[it].y;
            }
            #pragma unroll
            for (int mi2 = 0; mi2 < 2; mi2++)
                #pragma unroll
                for (int ki = 0; ki < 2; ki++)
                    afCur[mi2][ki] = afNext[mi2][ki];
        }
        __syncthreads();
    }

    const int groupID = lane >> 2;
    const int tig = lane & 3;
    #pragma unroll
    for (int mi2 = 0; mi2 < 2; mi2++) {
        const int row0 = rowBase + warpM * 32 + mi2 * 16 + groupID;
        #pragma unroll
        for (int nj = 0; nj < 8; nj++) {
            const int col = colBase + warpN * 64 + nj * 8 + tig * 2;
            float2 lo = make_float2(acc[mi2][nj][0], acc[mi2][nj][1]);
            float2 hi = make_float2(acc[mi2][nj][2], acc[mi2][nj][3]);
            float2 bz = *reinterpret_cast<const float2*>(&bias[col]);
            float2 r0 = *reinterpret_cast<const float2*>(&res[(size_t)row0 * C_ + col]);
            float2 r1 = *reinterpret_cast<const float2*>(&res[(size_t)(row0 + 8) * C_ + col]);
            lo.x += bz.x + r0.x; lo.y += bz.y + r0.y;
            hi.x += bz.x + r1.x; hi.y += bz.y + r1.y;
            *reinterpret_cast<float2*>(&C[(size_t)row0 * C_ + col]) = lo;
            *reinterpret_cast<float2*>(&C[(size_t)(row0 + 8) * C_ + col]) = hi;
        }
    }
}

// ---------------------------------------------------------------------------
// FP16 flash attention: register-resident P, ex2.f16x2 softmax, l via a
// ones-column V atom (tensor-pipe row-sums; no shuffles), output written as
// the fp16 fragment blob consumed directly by gemm3.
// Smem (u32): sKV 2 x (K 1536 + V 1792) @0 ; sQ 48x128 @6656.
// Total 12800 u32 = 51200 B. V atom 24..27 of each buffer = fp16 ones.
// ---------------------------------------------------------------------------
#define ATTN_SMEM_BYTES (12800 * 4)
#define KVBUF 3328

__device__ __forceinline__ void attn_ldg_kv(
    const float* __restrict__ kvbase, int m0, int tid,
    float4* kf4, float4* vf4)
{
    #pragma unroll
    for (int it = 0; it < 3; it++) {
        int idx = tid + it * 256;
        int n = idx / 12, f4 = idx - n * 12;
        const float* p = kvbase + (size_t)(m0 + n) * 2 * C_ + f4 * 4;
        kf4[it] = *reinterpret_cast<const float4*>(p);
        vf4[it] = *reinterpret_cast<const float4*>(p + C_);
    }
}

__device__ __forceinline__ void attn_scatter_kv(
    uint32_t* __restrict__ sKb, int tid, const float4* kf4, const float4* vf4)
{
    __half* sVh = reinterpret_cast<__half*>(sKb + 1536);
    #pragma unroll
    for (int it = 0; it < 3; it++) {
        int idx = tid + it * 256;
        int n = idx / 12, f4 = idx - n * 12;
        {
            int nj = n >> 3, g = n & 7, ki = f4 >> 2;
            int j = (f4 >> 1) & 1, t0 = 2 * (f4 & 1);
            int kb = (nj * 3 + ki) * 64 + j;
            sKb[kb + (g * 4 + t0) * 2]     = packh2(kf4[it].x, kf4[it].y);
            sKb[kb + (g * 4 + t0 + 1) * 2] = packh2(kf4[it].z, kf4[it].w);
        }
        {
            int kv = n >> 4, lk = n & 15;
            int jv = lk >> 3, tv = (lk & 7) >> 1, pos = lk & 1;
            float vv[4] = {vf4[it].x, vf4[it].y, vf4[it].z, vf4[it].w};
            #pragma unroll
            for (int i = 0; i < 4; i++) {
                int d = 4 * f4 + i;
                int ni = d >> 3, gd = d & 7;
                sVh[(((ni * 4 + kv) * 64 + (gd * 4 + tv) * 2 + jv) << 1) + pos] =
                    __float2half_rn(vv[i]);
            }
        }
    }
}

__global__ __launch_bounds__(256, 1) void attn_mma_kernel(
    const float* __restrict__ q, const float* __restrict__ kv,
    uint32_t* __restrict__ xf)
{
    extern __shared__ __align__(16) uint32_t smu[];
    uint32_t* sKV = smu;            // 2 x 3328 (K 1536 + V 1792)
    uint32_t* sQ  = smu + 2 * KVBUF;

    const int tid = threadIdx.x;
    const int wid = tid >> 5;
    const int lane = tid & 31;
    const int b = blockIdx.z, h = blockIdx.y;
    const int n0 = blockIdx.x * 256;
    const float qscale = 0.144337567297406441127f * 1.44269504088896340736f;

    // ones atoms (V ni=6, kk 0..3) in both buffers
    sKV[0 * KVBUF + 3072 + tid] = 0x3C003C00u;
    sKV[1 * KVBUF + 3072 + tid] = 0x3C003C00u;

    // ---- stage Q into fp16 A-frag atoms ----
    {
        const float* qbase = q + ((size_t)(b * N_ + n0)) * C_ + h * HD_;
        #pragma unroll
        for (int it = 0; it < 12; it++) {
            int idx = tid + it * 256;
            int m = idx / 12, f4 = idx - m * 12;
            float4 v = *reinterpret_cast<const float4*>(qbase + (size_t)m * C_ + f4 * 4);
            int mi = m >> 4, lr = m & 15, g = lr & 7;
            int ki = f4 >> 2;
            int r0 = (lr >> 3) + 2 * ((f4 >> 1) & 1);
            int t0 = 2 * (f4 & 1);
            int base = (mi * 3 + ki) * 128 + r0;
            sQ[base + (g * 4 + t0) * 4]     = packh2(v.x * qscale, v.y * qscale);
            sQ[base + (g * 4 + t0 + 1) * 4] = packh2(v.z * qscale, v.w * qscale);
        }
    }
    __syncthreads();

    uint32_t qf[2][3][4];
    #pragma unroll
    for (int mi2 = 0; mi2 < 2; mi2++)
        #pragma unroll
        for (int ki = 0; ki < 3; ki++) {
            uint4 tq = *reinterpret_cast<const uint4*>(
                &sQ[((wid * 2 + mi2) * 3 + ki) * 128 + lane * 4]);
            qf[mi2][ki][0] = tq.x; qf[mi2][ki][1] = tq.y;
            qf[mi2][ki][2] = tq.z; qf[mi2][ki][3] = tq.w;
        }

    const float* kvbase = kv + ((size_t)(b * M_)) * 2 * C_ + h * HD_;
    float4 kf4[3], vf4[3];
    attn_ldg_kv(kvbase, 0, tid, kf4, vf4);
    attn_scatter_kv(sKV, tid, kf4, vf4);
    __syncthreads();

    float accO[2][7][4];   // ni=6 accumulates l (ones column)
    #pragma unroll
    for (int mi2 = 0; mi2 < 2; mi2++)
        #pragma unroll
        for (int ni = 0; ni < 7; ni++)
            #pragma unroll
            for (int r = 0; r < 4; r++) accO[mi2][ni][r] = 0.f;

    for (int c = 0; c < 16; c++) {
        uint32_t* sK = sKV + (c & 1) * KVBUF;
        uint32_t* sV = sK + 1536;

        if (c < 15)
            attn_ldg_kv(kvbase, (c + 1) * 64, tid, kf4, vf4);

        // ---- QK^T ----
        float accS[2][8][4];
        #pragma unroll
        for (int mi2 = 0; mi2 < 2; mi2++)
            #pragma unroll
            for (int nj = 0; nj < 8; nj++)
                #pragma unroll
                for (int r = 0; r < 4; r++) accS[mi2][nj][r] = 0.f;
        #pragma unroll
        for (int nj = 0; nj < 8; nj++) {
            #pragma unroll
            for (int ki = 0; ki < 3; ki++) {
                uint2 tb = *reinterpret_cast<const uint2*>(
                    &sK[(nj * 3 + ki) * 64 + lane * 2]);
                uint32_t bf[2] = {tb.x, tb.y};
                mma_f16(accS[0][nj], qf[0][ki], bf);
                mma_f16(accS[1][nj], qf[1][ki], bf);
            }
        }

        // ---- softmax: half2-pack scores, one ex2.f16x2 per pair ----
        uint32_t paf[2][8][2];
        #pragma unroll
        for (int mi2 = 0; mi2 < 2; mi2++)
            #pragma unroll
            for (int nj = 0; nj < 8; nj++) {
                paf[mi2][nj][0] = ex2h2(packh2(accS[mi2][nj][0], accS[mi2][nj][1]));
                paf[mi2][nj][1] = ex2h2(packh2(accS[mi2][nj][2], accS[mi2][nj][3]));
            }

        // ---- PV (+ ones column => l in accO[*][6]) ----
        #pragma unroll
        for (int kk = 0; kk < 4; kk++) {
            uint32_t af[2][4];
            #pragma unroll
            for (int mi2 = 0; mi2 < 2; mi2++) {
                af[mi2][0] = paf[mi2][2 * kk][0];
                af[mi2][1] = paf[mi2][2 * kk][1];
                af[mi2][2] = paf[mi2][2 * kk + 1][0];
                af[mi2][3] = paf[mi2][2 * kk + 1][1];
            }
            #pragma unroll
            for (int ni = 0; ni < 7; ni++) {
                uint2 tb = *reinterpret_cast<const uint2*>(
                    &sV[(ni * 4 + kk) * 64 + lane * 2]);
                uint32_t bf[2] = {tb.x, tb.y};
                mma_f16(accO[0][ni], af[0], bf);
                mma_f16(accO[1][ni], af[1], bf);
            }
        }

        if (c < 15)
            attn_scatter_kv(sKV + ((c + 1) & 1) * KVBUF, tid, kf4, vf4);
        __syncthreads();
    }

    // ---- normalize + store as fp16 fragment blob (no shuffles: l = accO[6]) ----
    #pragma unroll
    for (int mi2 = 0; mi2 < 2; mi2++) {
        const float inv0 = 1.0f / accO[mi2][6][0];
        const float inv1 = 1.0f / accO[mi2][6][2];
        const int rowblk = (b * N_ + n0 + wid * 32 + mi2 * 16) >> 4;
        uint32_t* dstbase = xf + ((size_t)rowblk * 24 + h * 3) * 128 + lane * 4;
        #pragma unroll
        for (int ni = 0; ni < 6; ni++) {
            uint2 v;
            v.x = packh2(accO[mi2][ni][0] * inv0, accO[mi2][ni][1] * inv0);
            v.y = packh2(accO[mi2][ni][2] * inv1, accO[mi2][ni][3] * inv1);
            *reinterpret_cast<uint2*>(dstbase + (ni >> 1) * 128 + (ni & 1) * 2) = v;
        }
    }
}

// ---------------------------------------------------------------------------
// Launch
// ---------------------------------------------------------------------------
extern "C" void kernel_launch(void* const* d_in, const int* in_sizes, int n_in,
                              void* d_out, int out_size)
{
    const float* q_x   = (const float*)d_in[0];  // [4,4096,384]
    const float* kv_x  = (const float*)d_in[1];  // [4,1024,384]
    const float* Wq    = (const float*)d_in[2];  // [384,384]
    const float* Wkv   = (const float*)d_in[3];  // [384,768]
    const float* Wproj = (const float*)d_in[4];  // [384,384]
    const float* bproj = (const float*)d_in[5];  // [384]
    float* out = (float*)d_out;                  // [4,4096,384]

    float *gq, *gkv;
    uint32_t* gxf;
    __half *gwqt, *gwkvt, *gwpt;
    cudaGetSymbolAddress((void**)&gq,   g_q);
    cudaGetSymbolAddress((void**)&gkv,  g_kv);
    cudaGetSymbolAddress((void**)&gxf,  g_xf);
    cudaGetSymbolAddress((void**)&gwqt, g_wqt);
    cudaGetSymbolAddress((void**)&gwkvt,g_wkvt);
    cudaGetSymbolAddress((void**)&gwpt, g_wpt);

    cudaFuncSetAttribute(attn_mma_kernel,
                         cudaFuncAttributeMaxDynamicSharedMemorySize,
                         ATTN_SMEM_BYTES);
    cudaFuncSetAttribute(tc_gemm12_kernel,
                         cudaFuncAttributeMaxDynamicSharedMemorySize,
                         GEMM_SMEM_BYTES);

    // 0) weight transposes + fp16 conversion
    transpose_all_kernel<<<576, dim3(32, 8)>>>(Wq, Wkv, Wproj, gwqt, gwkvt, gwpt);

    // 1+2) q and kv projections in one launch
    tc_gemm12_kernel<<<576, 256, GEMM_SMEM_BYTES>>>(
        q_x, gwqt, gq, kv_x, gwkvt, gkv);

    // 3) attention -> fp16 fragment blob
    attn_mma_kernel<<<dim3(N_ / 256, H_, B_), 256, ATTN_SMEM_BYTES>>>(gq, gkv, gxf);

    // 4) out = blob @ Wproj^T + bias + residual(g_q)
    tc_gemm3_kernel<<<dim3(3, 128), 256>>>(gxf, gwpt, out, bproj, gq);
}